// round 3
// baseline (speedup 1.0000x reference)
#include <cuda_runtime.h>
#include <math.h>

// Problem constants (fixed by the reference)
#define HH 512
#define WW 512
#define HP 64
#define WP 2048
#define BB 4
#define CC 64
#define HW (HH * WW)          // 262144 cart pixels per plane
#define PLANE (HP * WP)       // 131072 polar elements per plane

// One fused kernel. Thread t handles 4 consecutive x pixels of row y, batch b,
// looping all 64 channels. The polar->cart map is recomputed analytically:
//  - mask (index_y > 0) is replicated BITWISE vs numpy (exact f32 ops only,
//    forced IEEE via _rn intrinsics so fast-math can't perturb it)
//  - the atan2-based x coordinate only needs continuity (bilinear is
//    continuous across cell boundaries), so ulp diffs are harmless.
__global__ void __launch_bounds__(128)
k_fused(const float* __restrict__ polar,
        const float* __restrict__ ref,
        float*       __restrict__ out) {
    const int y  = blockIdx.y;
    const int b  = blockIdx.z;
    const int x4 = threadIdx.x * 4;          // 128 threads * 4 px = 512 = WW

    // numpy: c1 = float32(H/2 * sqrt(2.0))
    const float c1 = 362.03867196751236f;
    const float PIf = 3.14159265358979323846f;   // rounds to f32(np.pi)

    int   pk[4];
    float w00[4], w01[4], w10[4], w11[4];
    bool  mapped[4];

    const float yyc = ((float)y - 256.0f) + 0.5f;

    #pragma unroll
    for (int j = 0; j < 4; ++j) {
        const int x = x4 + j;
        const float xxc = ((float)x - 256.0f) + 0.5f;

        // depth: exact squares/sum + correctly-rounded sqrt => bitwise == numpy
        float d2    = __fadd_rn(__fmul_rn(xxc, xxc), __fmul_rn(yyc, yyc));
        float depth = __fsqrt_rn(d2);
        // index_y = depth / c1 * 67 - 3   (each step f32, IEEE)
        float index_y = __fsub_rn(__fmul_rn(__fdiv_rn(depth, c1), 67.0f), 3.0f);
        mapped[j] = (index_y > 0.0f);

        // x coordinate chain (continuity-tolerant)
        float phi     = PIf - atan2f(yyc, xxc);
        float index_x = phi / PIf / 2.0f * (float)WP;
        float gx  = index_x / (float)WP * 2.0f - 1.0f;
        float gy  = -(index_y / (float)HP * 2.0f - 1.0f);
        float ixf = (gx + 1.0f) * ((WP - 1) * 0.5f);
        float iyf = (gy + 1.0f) * ((HP - 1) * 0.5f);

        float x0f = floorf(ixf);
        float y0f = floorf(iyf);
        float wx  = ixf - x0f;
        float wy  = iyf - y0f;
        int   x0  = (int)x0f;
        int   y0  = (int)y0f;

        // iyf is analytically in (0.13, 63) -> y0 in [0,62]; clamp = safety.
        y0 = min(max(y0, 0), HP - 2);
        // x0 in [0,2046] analytically; the wx-corrected clamp is exact at the
        // boundary (bilinear weight continuity).
        if (x0 < 0)      { x0 = 0;      wx = 0.0f; }
        if (x0 > WP - 2) { x0 = WP - 2; wx = 1.0f; }

        float wxm = 1.0f - wx, wym = 1.0f - wy;
        w00[j] = wxm * wym;
        w01[j] = wx  * wym;
        w10[j] = wxm * wy;
        w11[j] = wx  * wy;
        pk[j]  = y0 * WP + x0;
    }

    const size_t obase  = ((size_t)b * CC) * (size_t)HW + (size_t)y * WW + x4;
    const float* pbase  = polar + (size_t)b * CC * PLANE;
    const float* rbase  = ref + obase;
    float*       optr   = out + obase;

    #pragma unroll 2
    for (int c = 0; c < CC; ++c) {
        float4 r;
        float v[4];
        #pragma unroll
        for (int j = 0; j < 4; ++j) {
            if (mapped[j]) {
                const float* pp = pbase + pk[j];
                float v00 = __ldg(pp);
                float v01 = __ldg(pp + 1);
                float v10 = __ldg(pp + WP);
                float v11 = __ldg(pp + WP + 1);
                v[j] = v00 * w00[j] + v01 * w01[j] + v10 * w10[j] + v11 * w11[j];
            } else {
                v[j] = __ldg(rbase + j);
            }
        }
        r.x = v[0]; r.y = v[1]; r.z = v[2]; r.w = v[3];
        __stcs((float4*)optr, r);        // streaming: don't pollute L2
        pbase += PLANE;
        rbase += HW;
        optr  += HW;
    }
}

extern "C" void kernel_launch(void* const* d_in, const int* in_sizes, int n_in,
                              void* d_out, int out_size) {
    const float* polar = (const float*)d_in[0];   // [B,C,HP,WP]
    const float* ref   = (const float*)d_in[1];   // [B,C,H,W]
    float*       out   = (float*)d_out;           // [B,C,H,W]

    dim3 grid(1, HH, BB);     // 2048 blocks
    k_fused<<<grid, 128>>>(polar, ref, out);
}

// round 6
// speedup vs baseline: 1.7659x; 1.7659x over previous
#include <cuda_runtime.h>
#include <math.h>

// Problem constants (fixed by the reference)
#define HH 512
#define WW 512
#define HP 64
#define WP 2048
#define BB 4
#define CC 64
#define HW (HH * WW)          // 262144 cart pixels per plane
#define PLANE (HP * WP)       // 131072 polar elements per plane

// One fused kernel, ONE cart pixel per thread (narrow per-instruction address
// footprint -> fewer L1 wavefronts per gather LDG), 256-thread blocks for
// occupancy. Map recomputed analytically per thread, amortized over the
// 64-channel loop:
//  - mask (index_y > 0) replicated BITWISE vs numpy (exact f32 ops, _rn
//    intrinsics so fast-math can't perturb it)
//  - atan2-based x coordinate only needs continuity (bilinear is continuous
//    across cell boundaries), so ulp diffs are harmless.
__global__ void __launch_bounds__(256)
k_fused(const float* __restrict__ polar,
        const float* __restrict__ ref,
        float*       __restrict__ out) {
    const int x = blockIdx.x * 256 + threadIdx.x;
    const int y = blockIdx.y;
    const int b = blockIdx.z;

    // numpy: c1 = float32(H/2 * sqrt(2.0))
    const float c1  = 362.03867196751236f;
    const float PIf = 3.14159265358979323846f;   // rounds to f32(np.pi)

    const float yyc = ((float)y - 256.0f) + 0.5f;
    const float xxc = ((float)x - 256.0f) + 0.5f;

    // depth: exact squares/sum + correctly-rounded sqrt => bitwise == numpy
    float d2    = __fadd_rn(__fmul_rn(xxc, xxc), __fmul_rn(yyc, yyc));
    float depth = __fsqrt_rn(d2);
    // index_y = depth / c1 * 67 - 3   (each step f32, IEEE)
    float index_y = __fsub_rn(__fmul_rn(__fdiv_rn(depth, c1), 67.0f), 3.0f);
    const bool mapped = (index_y > 0.0f);

    // x coordinate chain (continuity-tolerant)
    float phi     = PIf - atan2f(yyc, xxc);
    float index_x = phi / PIf / 2.0f * (float)WP;
    float gx  = index_x / (float)WP * 2.0f - 1.0f;
    float gyv = -(index_y / (float)HP * 2.0f - 1.0f);
    float ixf = (gx  + 1.0f) * ((WP - 1) * 0.5f);
    float iyf = (gyv + 1.0f) * ((HP - 1) * 0.5f);

    float x0f = floorf(ixf);
    float y0f = floorf(iyf);
    float wx  = ixf - x0f;
    float wy  = iyf - y0f;
    int   x0  = (int)x0f;
    int   y0  = (int)y0f;

    // iyf analytically in (0.13, 63) -> y0 in [0,62]; clamp = safety.
    y0 = min(max(y0, 0), HP - 2);
    // x0 in [0,2046] analytically; boundary clamp preserves bilinear value.
    if (x0 < 0)      { x0 = 0;      wx = 0.0f; }
    if (x0 > WP - 2) { x0 = WP - 2; wx = 1.0f; }

    float wxm = 1.0f - wx, wym = 1.0f - wy;
    const float w00 = wxm * wym;
    const float w01 = wx  * wym;
    const float w10 = wxm * wy;
    const float w11 = wx  * wy;
    const int   pk  = y0 * WP + x0;

    const size_t obase = ((size_t)b * CC) * (size_t)HW + (size_t)y * WW + x;
    float*       o     = out + obase;

    if (mapped) {
        const float* pp = polar + (size_t)b * CC * PLANE + pk;
        #pragma unroll 4
        for (int c = 0; c < CC; ++c) {
            float v00 = __ldg(pp);
            float v01 = __ldg(pp + 1);
            float v10 = __ldg(pp + WP);
            float v11 = __ldg(pp + WP + 1);
            __stcs(o, v00 * w00 + v01 * w01 + v10 * w10 + v11 * w11);
            pp += PLANE;
            o  += HW;
        }
    } else {
        // unmapped pixel (center disk, ~0.3%): pass through ref_feat
        const float* r = ref + obase;
        #pragma unroll 8
        for (int c = 0; c < CC; ++c) {
            __stcs(o, __ldg(r));
            r += HW;
            o += HW;
        }
    }
}

extern "C" void kernel_launch(void* const* d_in, const int* in_sizes, int n_in,
                              void* d_out, int out_size) {
    const float* polar = (const float*)d_in[0];   // [B,C,HP,WP]
    const float* ref   = (const float*)d_in[1];   // [B,C,H,W]
    float*       out   = (float*)d_out;           // [B,C,H,W]

    dim3 grid(WW / 256, HH, BB);   // (2, 512, 4) = 4096 blocks
    k_fused<<<grid, 256>>>(polar, ref, out);
}

// round 7
// speedup vs baseline: 2.1759x; 1.2322x over previous
#include <cuda_runtime.h>
#include <math.h>

// Problem constants (fixed by the reference)
#define HH 512
#define WW 512
#define HP 64
#define WP 2048
#define BB 4
#define CC 64
#define HW (HH * WW)          // 262144 cart pixels per plane
#define PLANE (HP * WP)       // 131072 polar elements per plane

// Block = 256 threads covering a 32(x) x 8(y) cart tile for one b.
// Warp lanes form an 8x4 patch (narrow polar footprint per gather LDG);
// stores are re-coalesced through a bank-conflict-free smem tile
// (8 channels x 8 rows x 32 cols, row stride 40).
__global__ void __launch_bounds__(256)
k_fused(const float* __restrict__ polar,
        const float* __restrict__ ref,
        float*       __restrict__ out) {
    __shared__ float sbuf[8 * 8 * 40];      // [g][yy][xx], stride 40

    const int tid  = threadIdx.x;
    const int warp = tid >> 5;
    const int lane = tid & 31;

    // warp tile: 4 warps across x (8 px each), 2 down y (4 rows each)
    const int tx = ((warp & 3) << 3) | (lane & 7);   // 0..31 within tile
    const int ty = ((warp >> 2) << 2) | (lane >> 3); // 0..7  within tile

    const int bx = blockIdx.x;       // 16 tiles of 32 in x
    const int by = blockIdx.y;       // 64 tiles of 8 in y
    const int b  = blockIdx.z;

    const int x = (bx << 5) + tx;
    const int y = (by << 3) + ty;

    // ---- analytic map (mask chain bitwise == numpy) ----
    const float c1  = 362.03867196751236f;           // f32(256*sqrt(2))
    const float PIf = 3.14159265358979323846f;       // f32(np.pi)

    const float yyc = ((float)y - 256.0f) + 0.5f;
    const float xxc = ((float)x - 256.0f) + 0.5f;

    float d2    = __fadd_rn(__fmul_rn(xxc, xxc), __fmul_rn(yyc, yyc));
    float depth = __fsqrt_rn(d2);
    float index_y = __fsub_rn(__fmul_rn(__fdiv_rn(depth, c1), 67.0f), 3.0f);
    const bool mapped = (index_y > 0.0f);

    float phi     = PIf - atan2f(yyc, xxc);
    float index_x = phi / PIf / 2.0f * (float)WP;
    float gx  = index_x / (float)WP * 2.0f - 1.0f;
    float gyv = -(index_y / (float)HP * 2.0f - 1.0f);
    float ixf = (gx  + 1.0f) * ((WP - 1) * 0.5f);
    float iyf = (gyv + 1.0f) * ((HP - 1) * 0.5f);

    float x0f = floorf(ixf);
    float y0f = floorf(iyf);
    float wx  = ixf - x0f;
    float wy  = iyf - y0f;
    int   x0  = (int)x0f;
    int   y0  = (int)y0f;

    y0 = min(max(y0, 0), HP - 2);
    if (x0 < 0)      { x0 = 0;      wx = 0.0f; }
    if (x0 > WP - 2) { x0 = WP - 2; wx = 1.0f; }

    float wxm = 1.0f - wx, wym = 1.0f - wy;
    const float w00 = wxm * wym;
    const float w01 = wx  * wym;
    const float w10 = wxm * wy;
    const float w11 = wx  * wy;
    const int   pk  = y0 * WP + x0;

    const float* pbase = polar + (size_t)b * CC * PLANE + pk;
    const float* rbase = ref + ((size_t)b * CC) * HW + (size_t)y * WW + x;
    const size_t obase_blk = ((size_t)b * CC) * HW
                           + (size_t)(by << 3) * WW + (bx << 5);
    const int sidx = ty * 40 + tx;   // conflict-free for 8x4 patches

    for (int cg = 0; cg < 8; ++cg) {
        // ---- gather phase: 8 channels into smem ----
        if (mapped) {
            const float* pp = pbase + (size_t)(cg << 3) * PLANE;
            #pragma unroll
            for (int g = 0; g < 8; ++g) {
                float v00 = __ldg(pp);
                float v01 = __ldg(pp + 1);
                float v10 = __ldg(pp + WP);
                float v11 = __ldg(pp + WP + 1);
                sbuf[g * (8 * 40) + sidx] =
                    v00 * w00 + v01 * w01 + v10 * w10 + v11 * w11;
                pp += PLANE;
            }
        } else {
            const float* r = rbase + (size_t)(cg << 3) * HW;
            #pragma unroll
            for (int g = 0; g < 8; ++g) {
                sbuf[g * (8 * 40) + sidx] = __ldg(r);
                r += HW;
            }
        }
        __syncthreads();

        // ---- store phase: fully coalesced 128B rows ----
        #pragma unroll
        for (int i = 0; i < 8; ++i) {
            int idx = i * 256 + tid;       // 2048 = 8g * 8y * 32x
            int xx  = idx & 31;
            int yy  = (idx >> 5) & 7;
            int g   = idx >> 8;
            __stcs(out + obase_blk + (size_t)((cg << 3) + g) * HW
                       + (size_t)yy * WW + xx,
                   sbuf[(g * 8 + yy) * 40 + xx]);
        }
        __syncthreads();
    }
}

extern "C" void kernel_launch(void* const* d_in, const int* in_sizes, int n_in,
                              void* d_out, int out_size) {
    const float* polar = (const float*)d_in[0];   // [B,C,HP,WP]
    const float* ref   = (const float*)d_in[1];   // [B,C,H,W]
    float*       out   = (float*)d_out;           // [B,C,H,W]

    dim3 grid(WW / 32, HH / 8, BB);   // (16, 64, 4) = 4096 blocks
    k_fused<<<grid, 256>>>(polar, ref, out);
}